// round 10
// baseline (speedup 1.0000x reference)
#include <cuda_runtime.h>
#include <cuda_bf16.h>
#include <math.h>
#include <stdint.h>

#define Bn 64
#define Sn 1024
#define In 256
#define Hn 256
#define Gn 768   // 3*H

// packed f32x2 FMA (sm_103a)
#define FMA2(d, a, b, c) \
    asm("fma.rn.f32x2 %0, %1, %2, %3;" : "=l"(d) : "l"(a), "l"(b), "l"(c))
#define ADD2(d, a, b) \
    asm("add.rn.f32x2 %0, %1, %2;" : "=l"(d) : "l"(a), "l"(b))
#define UNPK(lo, hi, v) \
    asm("mov.b64 {%0,%1}, %2;" : "=f"(lo), "=f"(hi) : "l"(v))

// Scratch for input-side gate projections xg[B][S][768] (reused by both layers).
__device__ float g_xg[(size_t)Bn * Sn * Gn];

// ---------------------------------------------------------------------------
// GEMM: C[m][n] = sum_k X[m][k]*W[n][k] + bias[n];  M=65536, N=768, K=256.
// 64x64 tile, 256 threads, 4x4 fragments, f32x2 packed FMAs.
// ---------------------------------------------------------------------------
__global__ void __launch_bounds__(256)
gemm768_kernel(const float* __restrict__ X, int lda,
               const float* __restrict__ W,
               const float* __restrict__ bias)
{
    __shared__ __align__(16) float Xs[64 * 70];
    __shared__ __align__(16) float Ws[64 * 70];

    const int tid = threadIdx.x;
    const int tx = tid & 15;
    const int ty = tid >> 4;
    const int m0 = blockIdx.y * 64;
    const int n0 = blockIdx.x * 64;

    const int kq = tid & 15;
    const int rr = tid >> 4;

    uint64_t acc[4][4] = {};

    for (int kc = 0; kc < 256; kc += 64) {
#pragma unroll
        for (int jj = 0; jj < 4; jj++) {
            int row = rr + 16 * jj;
            float4 xv = *(const float4*)&X[(size_t)(m0 + row) * lda + kc + kq * 4];
            float4 wv = *(const float4*)&W[(size_t)(n0 + row) * 256 + kc + kq * 4];
            *(float2*)&Xs[row * 70 + kq * 4]     = make_float2(xv.x, xv.y);
            *(float2*)&Xs[row * 70 + kq * 4 + 2] = make_float2(xv.z, xv.w);
            *(float2*)&Ws[row * 70 + kq * 4]     = make_float2(wv.x, wv.y);
            *(float2*)&Ws[row * 70 + kq * 4 + 2] = make_float2(wv.z, wv.w);
        }
        __syncthreads();

#pragma unroll 8
        for (int kp = 0; kp < 32; kp++) {
            uint64_t xf[4], wf[4];
#pragma unroll
            for (int jj = 0; jj < 4; jj++)
                xf[jj] = *(const uint64_t*)&Xs[(ty + 16 * jj) * 70 + 2 * kp];
#pragma unroll
            for (int ii = 0; ii < 4; ii++)
                wf[ii] = *(const uint64_t*)&Ws[(tx + 16 * ii) * 70 + 2 * kp];
#pragma unroll
            for (int jj = 0; jj < 4; jj++)
#pragma unroll
                for (int ii = 0; ii < 4; ii++)
                    FMA2(acc[jj][ii], xf[jj], wf[ii], acc[jj][ii]);
        }
        __syncthreads();
    }

#pragma unroll
    for (int jj = 0; jj < 4; jj++) {
        int m = m0 + ty + 16 * jj;
#pragma unroll
        for (int ii = 0; ii < 4; ii++) {
            int n = n0 + tx + 16 * ii;
            float lo, hi;
            UNPK(lo, hi, acc[jj][ii]);
            g_xg[(size_t)m * Gn + n] = lo + hi + bias[n];
        }
    }
}

// ---------------------------------------------------------------------------
// Recurrence. Cluster of 4 CTAs = 2 batch rows; 32 clusters = 128 CTAs.
// CTA rank r owns hidden cols [r*64, r*64+64); its 192 W_hh gate rows live in
// registers (64 x b64/thread). Per step:
//   dot (FMA2) -> pacc -> gates -> LOCAL store of own h slice -> sync
//   -> 3 remote mbarrier arrives (release.cluster, fire-and-forget)
//   -> global output stores (off critical path)
//   -> wait own mbarrier (acquire.cluster, 3 peer arrivals)
//   -> PULL 3 peer slices via ld.shared::cluster.b64 -> local smem -> sync
// No barrier.cluster and no remote stores in the loop => no drain stalls.
// ---------------------------------------------------------------------------
__device__ __forceinline__ void wait_parity_cluster(uint32_t mbar, uint32_t parity)
{
    uint32_t done;
    asm volatile(
        "{\n\t.reg .pred p;\n\t"
        "mbarrier.try_wait.parity.acquire.cluster.shared::cta.b64 p, [%1], %2;\n\t"
        "selp.b32 %0, 1, 0, p;\n\t}"
        : "=r"(done) : "r"(mbar), "r"(parity) : "memory");
    if (!done) {
        asm volatile(
            "{\n\t.reg .pred P1;\n\t"
            "W_%=:\n\t"
            "mbarrier.try_wait.parity.acquire.cluster.shared::cta.b64 P1, [%0], %1, 0x989680;\n\t"
            "@P1 bra.uni D_%=;\n\t"
            "bra.uni W_%=;\n\t"
            "D_%=:\n\t}"
            :: "r"(mbar), "r"(parity) : "memory");
    }
}

__global__ void __cluster_dims__(4, 1, 1) __launch_bounds__(384, 1)
gru_rec_kernel(const float* __restrict__ Whh,   // [768][256]
               const float* __restrict__ bhh,   // [768]
               float* __restrict__ outA, int pitchA, int colOffA,
               float* __restrict__ outB)        // second copy (pitch Hn) or null
{
    __shared__ __align__(16) float hb[2 * 2 * 256];  // [buf][batch][k]
    __shared__ float pacc[2 * 192 * 2];              // [kb][l][batch]
    __shared__ float bh[192];
    __shared__ __align__(8) uint64_t bar;            // step mbarrier (3 peer arrivals)

    const int tid = threadIdx.x;
    uint32_t rank;
    asm("mov.u32 %0, %%cluster_ctarank;" : "=r"(rank));
    const int cid   = blockIdx.x >> 2;
    const int b0    = cid * 2;
    const int cbase = (int)rank * 64;

    const int l   = tid % 192;
    const int kb  = tid / 192;            // 0 or 1
    const int kst = kb * 128;
    const int g   = (l < 64) ? (cbase + l)
                  : (l < 128) ? (256 + cbase + (l - 64))
                              : (512 + cbase + (l - 128));

    // ---- weights -> registers (64 x b64 = 128 floats per thread) ----
    uint64_t w[64];
    {
        const uint64_t* wsrc = (const uint64_t*)(Whh + (size_t)g * 256 + kst);
#pragma unroll
        for (int i = 0; i < 64; i++) w[i] = wsrc[i];
    }

    if (tid < 192) bh[l] = bhh[g];
    for (int i = tid; i < 1024; i += 384) hb[i] = 0.0f;   // h0 = 0, both bufs

    uint32_t bar_local = (uint32_t)__cvta_generic_to_shared(&bar);
    if (tid == 0) {
        asm volatile("mbarrier.init.shared.b64 [%0], 3;" :: "r"(bar_local) : "memory");
    }
    __syncthreads();

    // remote addresses (hb and bar) for all 4 cluster ranks
    uint32_t hb_local = (uint32_t)__cvta_generic_to_shared(hb);
    uint32_t remote_hb[4], remote_bar[4];
#pragma unroll
    for (int r2 = 0; r2 < 4; r2++) {
        asm("mapa.shared::cluster.u32 %0, %1, %2;" : "=r"(remote_hb[r2])  : "r"(hb_local),  "r"(r2));
        asm("mapa.shared::cluster.u32 %0, %1, %2;" : "=r"(remote_bar[r2]) : "r"(bar_local), "r"(r2));
    }

    // one-time cluster sync: everyone's hb zeroed + bars initialized
    asm volatile("barrier.cluster.arrive.aligned;" ::: "memory");
    asm volatile("barrier.cluster.wait.aligned;"   ::: "memory");

    // per-thread roles
    const int j    = tid & 63;            // gate column (tid<128)
    const int bsel = (tid >> 6) & 1;
    const int gcol = cbase + j;
    const float* xp = g_xg + ((size_t)(b0 + bsel) * Sn) * Gn + gcol;
    float* oA = outA + ((size_t)(b0 + bsel) * Sn) * pitchA + colOffA + gcol;
    float* oB = outB ? outB + ((size_t)(b0 + bsel) * Sn) * Hn + gcol : nullptr;

    // arrive targets for tid<3: the 3 peer ranks
    const int arr_peer = (tid < 3) ? (tid + (tid >= (int)rank ? 1 : 0)) : 0;

    // gather role (tid<192): pull peer p's slice pair
    const int gp   = tid >> 6;                         // 0..2
    const int gpr  = gp + (gp >= (int)rank ? 1 : 0);   // peer rank
    const int gq   = tid & 63;
    const int gb   = gq >> 5;                          // batch
    const int gpi  = gq & 31;                          // pair index in 64-col slice
    const int goff = gb * 256 + gpr * 64 + gpi * 2;    // float offset within a buffer

    for (int t = 0; t < Sn; t++) {
        const int cur = t & 1;
        const int nxt = cur ^ 1;

        // prefetch input-side gates (latency hidden under dot loop)
        float xr = 0.f, xz = 0.f, xn = 0.f;
        if (tid < 128) {
            xr = __ldg(xp);
            xz = __ldg(xp + 256);
            xn = __ldg(xp + 512);
        }

        // ---- packed dot over this thread's 128-k half, both batch rows ----
        const ulonglong2* h0p = (const ulonglong2*)(hb + cur * 512 + kst);
        const ulonglong2* h1p = (const ulonglong2*)(hb + cur * 512 + 256 + kst);
        uint64_t a0 = 0, a1 = 0, c0 = 0, c1 = 0;
#pragma unroll
        for (int i = 0; i < 32; i++) {
            ulonglong2 hA = h0p[i];
            ulonglong2 hB = h1p[i];
            FMA2(a0, w[2 * i],     hA.x, a0);
            FMA2(a1, w[2 * i + 1], hA.y, a1);
            FMA2(c0, w[2 * i],     hB.x, c0);
            FMA2(c1, w[2 * i + 1], hB.y, c1);
        }
        uint64_t s0, s1;
        ADD2(s0, a0, a1);
        ADD2(s1, c0, c1);
        float s0l, s0h, s1l, s1h;
        UNPK(s0l, s0h, s0);
        UNPK(s1l, s1h, s1);
        pacc[(kb * 192 + l) * 2 + 0] = s0l + s0h;
        pacc[(kb * 192 + l) * 2 + 1] = s1l + s1h;
        __syncthreads();

        // ---- gates + state update (128 threads: 64 cols x 2 batch) ----
        float hnew = 0.f;
        if (tid < 128) {
            float hr = pacc[(j)       * 2 + bsel] + pacc[(192 + j)       * 2 + bsel] + bh[j];
            float hz = pacc[(64 + j)  * 2 + bsel] + pacc[(192 + 64 + j)  * 2 + bsel] + bh[64 + j];
            float hn = pacc[(128 + j) * 2 + bsel] + pacc[(192 + 128 + j) * 2 + bsel] + bh[128 + j];

            float r = 1.0f / (1.0f + __expf(-(xr + hr)));
            float z = 1.0f / (1.0f + __expf(-(xz + hz)));
            float n = tanhf(xn + r * hn);

            float hold = hb[cur * 512 + bsel * 256 + gcol];
            hnew = (1.0f - z) * n + z * hold;

            // LOCAL store of own slice only (no remote pushes)
            hb[nxt * 512 + bsel * 256 + gcol] = hnew;
        }
        __syncthreads();   // own slice locally complete (BAR drains STS)

        // signal the 3 peers: "my step-t slice is ready" (release at cluster scope)
        if (t < Sn - 1 && tid < 3) {
            asm volatile("mbarrier.arrive.release.cluster.shared::cluster.b64 _, [%0];"
                         :: "r"(remote_bar[arr_peer]) : "memory");
        }

        // global output stores — off the inter-CTA critical path
        if (tid < 128) {
            *oA = hnew;
            oA += pitchA;
            if (oB) { *oB = hnew; oB += Hn; }
            xp += Gn;
        }

        if (t < Sn - 1) {
            // wait for all 3 peer slices of step t
            wait_parity_cluster(bar_local, (uint32_t)(t & 1));

            // pull peer slices into local hb[nxt]
            if (tid < 192) {
                uint64_t v;
                asm volatile("ld.shared::cluster.b64 %0, [%1];"
                             : "=l"(v) : "r"(remote_hb[gpr] + (uint32_t)((nxt * 512 + goff) * 4))
                             : "memory");
                *(uint64_t*)(hb + nxt * 512 + goff) = v;
            }
            __syncthreads();
        }
    }
}

// ---------------------------------------------------------------------------
// Launch: GEMM0 -> REC0 -> GEMM1 -> REC1.
// Output layout (tuple flattened): [ h2 (B,S,H) | concat(h1,h2) (B,S,2H) ].
// ---------------------------------------------------------------------------
extern "C" void kernel_launch(void* const* d_in, const int* in_sizes, int n_in,
                              void* d_out, int out_size)
{
    const float* inputs = (const float*)d_in[0];
    const float* W_ih0  = (const float*)d_in[1];
    const float* W_hh0  = (const float*)d_in[2];
    const float* b_ih0  = (const float*)d_in[3];
    const float* b_hh0  = (const float*)d_in[4];
    const float* W_ih1  = (const float*)d_in[5];
    const float* W_hh1  = (const float*)d_in[6];
    const float* b_ih1  = (const float*)d_in[7];
    const float* b_hh1  = (const float*)d_in[8];

    float* out    = (float*)d_out;
    float* h2     = out;                              // [B,S,H]
    float* concat = out + (size_t)Bn * Sn * Hn;       // [B,S,2H]

    (void)in_sizes; (void)n_in; (void)out_size;

    dim3 ggrid(Gn / 64, (Bn * Sn) / 64);   // 12 x 1024

    // Layer 0
    gemm768_kernel<<<ggrid, 256>>>(inputs, In, W_ih0, b_ih0);
    gru_rec_kernel<<<128, 384>>>(W_hh0, b_hh0, concat, 2 * Hn, 0, nullptr);

    // Layer 1: input is h1 living in concat (row pitch 512, cols 0..255)
    gemm768_kernel<<<ggrid, 256>>>(concat, 2 * Hn, W_ih1, b_ih1);
    gru_rec_kernel<<<128, 384>>>(W_hh1, b_hh1, concat, 2 * Hn, Hn, h2);
}

// round 15
// speedup vs baseline: 1.1765x; 1.1765x over previous
#include <cuda_runtime.h>
#include <cuda_bf16.h>
#include <math.h>
#include <stdint.h>

#define Bn 64
#define Sn 1024
#define In 256
#define Hn 256
#define Gn 768   // 3*H

// packed f32x2 FMA (sm_103a)
#define FMA2(d, a, b, c) \
    asm("fma.rn.f32x2 %0, %1, %2, %3;" : "=l"(d) : "l"(a), "l"(b), "l"(c))
#define ADD2(d, a, b) \
    asm("add.rn.f32x2 %0, %1, %2;" : "=l"(d) : "l"(a), "l"(b))
#define UNPK(lo, hi, v) \
    asm("mov.b64 {%0,%1}, %2;" : "=f"(lo), "=f"(hi) : "l"(v))

// Scratch for input-side gate projections xg[B][S][768] (reused by both layers).
__device__ float g_xg[(size_t)Bn * Sn * Gn];

// overflow-safe fast activations (MUFU EX2 based, ~1e-7 rel err)
__device__ __forceinline__ float sigmoid_f(float x) {
    return __fdividef(1.0f, 1.0f + __expf(-x));     // exp->inf => 0, safe
}
__device__ __forceinline__ float tanh_f(float x) {
    // 1 - 2/(e^{2x}+1): e->inf => 1; e->0 => -1; never NaN
    return 1.0f - __fdividef(2.0f, __expf(2.0f * x) + 1.0f);
}

// ---------------------------------------------------------------------------
// GEMM: C[m][n] = sum_k X[m][k]*W[n][k] + bias[n];  M=65536, N=768, K=256.
// 64x64 tile, 256 threads, 4x4 fragments, f32x2 packed FMAs.
// ---------------------------------------------------------------------------
__global__ void __launch_bounds__(256)
gemm768_kernel(const float* __restrict__ X, int lda,
               const float* __restrict__ W,
               const float* __restrict__ bias)
{
    __shared__ __align__(16) float Xs[64 * 70];
    __shared__ __align__(16) float Ws[64 * 70];

    const int tid = threadIdx.x;
    const int tx = tid & 15;
    const int ty = tid >> 4;
    const int m0 = blockIdx.y * 64;
    const int n0 = blockIdx.x * 64;

    const int kq = tid & 15;
    const int rr = tid >> 4;

    uint64_t acc[4][4] = {};

    for (int kc = 0; kc < 256; kc += 64) {
#pragma unroll
        for (int jj = 0; jj < 4; jj++) {
            int row = rr + 16 * jj;
            float4 xv = *(const float4*)&X[(size_t)(m0 + row) * lda + kc + kq * 4];
            float4 wv = *(const float4*)&W[(size_t)(n0 + row) * 256 + kc + kq * 4];
            *(float2*)&Xs[row * 70 + kq * 4]     = make_float2(xv.x, xv.y);
            *(float2*)&Xs[row * 70 + kq * 4 + 2] = make_float2(xv.z, xv.w);
            *(float2*)&Ws[row * 70 + kq * 4]     = make_float2(wv.x, wv.y);
            *(float2*)&Ws[row * 70 + kq * 4 + 2] = make_float2(wv.z, wv.w);
        }
        __syncthreads();

#pragma unroll 8
        for (int kp = 0; kp < 32; kp++) {
            uint64_t xf[4], wf[4];
#pragma unroll
            for (int jj = 0; jj < 4; jj++)
                xf[jj] = *(const uint64_t*)&Xs[(ty + 16 * jj) * 70 + 2 * kp];
#pragma unroll
            for (int ii = 0; ii < 4; ii++)
                wf[ii] = *(const uint64_t*)&Ws[(tx + 16 * ii) * 70 + 2 * kp];
#pragma unroll
            for (int jj = 0; jj < 4; jj++)
#pragma unroll
                for (int ii = 0; ii < 4; ii++)
                    FMA2(acc[jj][ii], xf[jj], wf[ii], acc[jj][ii]);
        }
        __syncthreads();
    }

#pragma unroll
    for (int jj = 0; jj < 4; jj++) {
        int m = m0 + ty + 16 * jj;
#pragma unroll
        for (int ii = 0; ii < 4; ii++) {
            int n = n0 + tx + 16 * ii;
            float lo, hi;
            UNPK(lo, hi, acc[jj][ii]);
            g_xg[(size_t)m * Gn + n] = lo + hi + bias[n];
        }
    }
}

// ---------------------------------------------------------------------------
// Recurrence. Cluster of 4 CTAs = 2 batch rows; 32 clusters = 128 CTAs.
// CTA rank r owns hidden cols [r*64, r*64+64); its 192 W_hh gate rows live in
// registers (64 x b64/thread). Per step:
//   dot (FMA2) -> pacc -> sync -> gates -> PUSH own slice to 3 peers
//   (st.shared::cluster, fire-and-forget; SKIPPED on the last step) + local
//   store -> sync -> 3 one-sided mbarrier.arrive.release.cluster to peers
//   -> global output stores (off the inter-CTA critical path)
//   -> wait local mbarrier (acquire, phase parity = t&1)
// No barrier.cluster in the loop (no ~490cyc wait, no per-step L1D flush),
// no remote loads. LIFETIME: remote pushes only at t<Sn-1; each such store is
// released by the same-step arrive and acquired by the peer's wait(t) before
// that peer can exit, so no remote store can target an exited CTA. A final
// barrier.cluster guards exit anyway.
// ---------------------------------------------------------------------------
__device__ __forceinline__ void wait_parity_acq(uint32_t mbar, uint32_t parity)
{
    uint32_t done;
    asm volatile(
        "{\n\t.reg .pred p;\n\t"
        "mbarrier.try_wait.parity.acquire.cluster.shared::cta.b64 p, [%1], %2;\n\t"
        "selp.b32 %0, 1, 0, p;\n\t}"
        : "=r"(done) : "r"(mbar), "r"(parity) : "memory");
    if (!done) {
        asm volatile(
            "{\n\t.reg .pred P1;\n\t"
            "W_%=:\n\t"
            "mbarrier.try_wait.parity.acquire.cluster.shared::cta.b64 P1, [%0], %1, 0x989680;\n\t"
            "@P1 bra.uni D_%=;\n\t"
            "bra.uni W_%=;\n\t"
            "D_%=:\n\t}"
            :: "r"(mbar), "r"(parity) : "memory");
    }
}

__global__ void __cluster_dims__(4, 1, 1) __launch_bounds__(384, 1)
gru_rec_kernel(const float* __restrict__ Whh,   // [768][256]
               const float* __restrict__ bhh,   // [768]
               float* __restrict__ outA, int pitchA, int colOffA,
               float* __restrict__ outB)        // second copy (pitch Hn) or null
{
    __shared__ __align__(16) float hb[2 * 2 * 256];  // [buf][batch][k]
    __shared__ float pacc[2 * 192 * 2];              // [kb][l][batch]
    __shared__ float bh[192];
    __shared__ __align__(8) uint64_t bar;            // step mbarrier (3 peer arrivals)

    const int tid = threadIdx.x;
    uint32_t rank;
    asm("mov.u32 %0, %%cluster_ctarank;" : "=r"(rank));
    const int cid   = blockIdx.x >> 2;
    const int b0    = cid * 2;
    const int cbase = (int)rank * 64;

    const int l   = tid % 192;
    const int kb  = tid / 192;            // 0 or 1
    const int kst = kb * 128;
    const int g   = (l < 64) ? (cbase + l)
                  : (l < 128) ? (256 + cbase + (l - 64))
                              : (512 + cbase + (l - 128));

    // ---- weights -> registers (64 x b64 = 128 floats per thread) ----
    uint64_t w[64];
    {
        const uint64_t* wsrc = (const uint64_t*)(Whh + (size_t)g * 256 + kst);
#pragma unroll
        for (int i = 0; i < 64; i++) w[i] = wsrc[i];
    }

    if (tid < 192) bh[l] = bhh[g];
    for (int i = tid; i < 1024; i += 384) hb[i] = 0.0f;   // h0 = 0, both bufs

    uint32_t bar_local = (uint32_t)__cvta_generic_to_shared(&bar);
    if (tid == 0) {
        asm volatile("mbarrier.init.shared.b64 [%0], 3;" :: "r"(bar_local) : "memory");
    }
    __syncthreads();

    // remote addresses for all 4 cluster ranks
    uint32_t hb_local = (uint32_t)__cvta_generic_to_shared(hb);
    uint32_t remote_hb[4], remote_bar[4];
#pragma unroll
    for (int r2 = 0; r2 < 4; r2++) {
        asm("mapa.shared::cluster.u32 %0, %1, %2;" : "=r"(remote_hb[r2])  : "r"(hb_local),  "r"(r2));
        asm("mapa.shared::cluster.u32 %0, %1, %2;" : "=r"(remote_bar[r2]) : "r"(bar_local), "r"(r2));
    }

    // one-time cluster sync: everyone's hb zeroed + bars initialized
    asm volatile("barrier.cluster.arrive.aligned;" ::: "memory");
    asm volatile("barrier.cluster.wait.aligned;"   ::: "memory");

    // per-thread roles
    const int j    = tid & 63;            // gate column (tid<128)
    const int bsel = (tid >> 6) & 1;
    const int gcol = cbase + j;
    const float* xp = g_xg + ((size_t)(b0 + bsel) * Sn) * Gn + gcol;
    float* oA = outA + ((size_t)(b0 + bsel) * Sn) * pitchA + colOffA + gcol;
    float* oB = outB ? outB + ((size_t)(b0 + bsel) * Sn) * Hn + gcol : nullptr;

    // 3 peer ranks (for pushes and arrives)
    int peers[3];
#pragma unroll
    for (int p = 0; p < 3; p++) peers[p] = p + (p >= (int)rank ? 1 : 0);
    const int arr_peer = (tid < 3) ? peers[tid] : 0;

    float hprev = 0.0f;   // own h column lives in a register (tid<128)

    for (int t = 0; t < Sn; t++) {
        const int cur = t & 1;
        const int nxt = cur ^ 1;
        const bool not_last = (t < Sn - 1);

        // prefetch input-side gates (latency hidden under dot loop)
        float xr = 0.f, xz = 0.f, xn = 0.f;
        if (tid < 128) {
            xr = __ldg(xp);
            xz = __ldg(xp + 256);
            xn = __ldg(xp + 512);
        }

        // ---- packed dot over this thread's 128-k half, both batch rows ----
        const ulonglong2* h0p = (const ulonglong2*)(hb + cur * 512 + kst);
        const ulonglong2* h1p = (const ulonglong2*)(hb + cur * 512 + 256 + kst);
        uint64_t a0 = 0, a1 = 0, c0 = 0, c1 = 0;
#pragma unroll
        for (int i = 0; i < 32; i++) {
            ulonglong2 hA = h0p[i];
            ulonglong2 hB = h1p[i];
            FMA2(a0, w[2 * i],     hA.x, a0);
            FMA2(a1, w[2 * i + 1], hA.y, a1);
            FMA2(c0, w[2 * i],     hB.x, c0);
            FMA2(c1, w[2 * i + 1], hB.y, c1);
        }
        uint64_t s0, s1;
        ADD2(s0, a0, a1);
        ADD2(s1, c0, c1);
        float s0l, s0h, s1l, s1h;
        UNPK(s0l, s0h, s0);
        UNPK(s1l, s1h, s1);
        pacc[(kb * 192 + l) * 2 + 0] = s0l + s0h;
        pacc[(kb * 192 + l) * 2 + 1] = s1l + s1h;
        __syncthreads();

        // ---- gates + state update (128 threads: 64 cols x 2 batch) ----
        float hnew = 0.f;
        if (tid < 128) {
            float hr = pacc[(j)       * 2 + bsel] + pacc[(192 + j)       * 2 + bsel] + bh[j];
            float hz = pacc[(64 + j)  * 2 + bsel] + pacc[(192 + 64 + j)  * 2 + bsel] + bh[64 + j];
            float hn = pacc[(128 + j) * 2 + bsel] + pacc[(192 + 128 + j) * 2 + bsel] + bh[128 + j];

            float r = sigmoid_f(xr + hr);
            float z = sigmoid_f(xz + hz);
            float n = tanh_f(xn + r * hn);

            hnew  = (1.0f - z) * n + z * hprev;
            hprev = hnew;

            if (not_last) {
                // local copy + push to the 3 peers' next buffer. Remote pushes
                // ONLY when a next step exists (peer lifetime guarantee).
                uint32_t off = (uint32_t)((nxt * 512 + bsel * 256 + gcol) * 4);
                hb[nxt * 512 + bsel * 256 + gcol] = hnew;
#pragma unroll
                for (int p = 0; p < 3; p++) {
                    asm volatile("st.shared::cluster.f32 [%0], %1;"
                                 :: "r"(remote_hb[peers[p]] + off), "f"(hnew));
                }
            }
        }
        __syncthreads();   // all pushes issued; local slice complete

        // one-sided signal: "my step-t slice is in YOUR smem" (release.cluster
        // makes this CTA's prior cluster stores visible to the acquiring waiter)
        if (not_last && tid < 3) {
            asm volatile("mbarrier.arrive.release.cluster.shared::cluster.b64 _, [%0];"
                         :: "r"(remote_bar[arr_peer]) : "memory");
        }

        // global output stores — off the inter-CTA critical path
        if (tid < 128) {
            *oA = hnew;
            oA += pitchA;
            if (oB) { *oB = hnew; oB += Hn; }
            xp += Gn;
        }

        // wait for the 3 peer slices of step t (local barrier, acquire)
        if (not_last) {
            wait_parity_acq(bar_local, (uint32_t)(t & 1));
        }
    }

    // lifetime guard: no CTA exits while peers might still touch its SMEM
    asm volatile("barrier.cluster.arrive.aligned;" ::: "memory");
    asm volatile("barrier.cluster.wait.aligned;"   ::: "memory");
}

// ---------------------------------------------------------------------------
// Launch: GEMM0 -> REC0 -> GEMM1 -> REC1.
// Output layout (tuple flattened): [ h2 (B,S,H) | concat(h1,h2) (B,S,2H) ].
// ---------------------------------------------------------------------------
extern "C" void kernel_launch(void* const* d_in, const int* in_sizes, int n_in,
                              void* d_out, int out_size)
{
    const float* inputs = (const float*)d_in[0];
    const float* W_ih0  = (const float*)d_in[1];
    const float* W_hh0  = (const float*)d_in[2];
    const float* b_ih0  = (const float*)d_in[3];
    const float* b_hh0  = (const float*)d_in[4];
    const float* W_ih1  = (const float*)d_in[5];
    const float* W_hh1  = (const float*)d_in[6];
    const float* b_ih1  = (const float*)d_in[7];
    const float* b_hh1  = (const float*)d_in[8];

    float* out    = (float*)d_out;
    float* h2     = out;                              // [B,S,H]
    float* concat = out + (size_t)Bn * Sn * Hn;       // [B,S,2H]

    (void)in_sizes; (void)n_in; (void)out_size;

    dim3 ggrid(Gn / 64, (Bn * Sn) / 64);   // 12 x 1024

    // Layer 0
    gemm768_kernel<<<ggrid, 256>>>(inputs, In, W_ih0, b_ih0);
    gru_rec_kernel<<<128, 384>>>(W_hh0, b_hh0, concat, 2 * Hn, 0, nullptr);

    // Layer 1: input is h1 living in concat (row pitch 512, cols 0..255)
    gemm768_kernel<<<ggrid, 256>>>(concat, 2 * Hn, W_ih1, b_ih1);
    gru_rec_kernel<<<128, 384>>>(W_hh1, b_hh1, concat, 2 * Hn, Hn, h2);
}

// round 16
// speedup vs baseline: 1.7052x; 1.4493x over previous
#include <cuda_runtime.h>
#include <cuda_bf16.h>
#include <math.h>
#include <stdint.h>

#define Bn 64
#define Sn 1024
#define In 256
#define Hn 256
#define Gn 768   // 3*H

// packed f32x2 FMA (sm_103a)
#define FMA2(d, a, b, c) \
    asm("fma.rn.f32x2 %0, %1, %2, %3;" : "=l"(d) : "l"(a), "l"(b), "l"(c))
#define ADD2(d, a, b) \
    asm("add.rn.f32x2 %0, %1, %2;" : "=l"(d) : "l"(a), "l"(b))
#define UNPK(lo, hi, v) \
    asm("mov.b64 {%0,%1}, %2;" : "=f"(lo), "=f"(hi) : "l"(v))

// Scratch for input-side gate projections xg[B][S][768] (reused by both layers).
__device__ float g_xg[(size_t)Bn * Sn * Gn];

// overflow-safe fast activations (MUFU EX2 based, ~1e-7 rel err)
__device__ __forceinline__ float sigmoid_f(float x) {
    return __fdividef(1.0f, 1.0f + __expf(-x));
}
__device__ __forceinline__ float tanh_f(float x) {
    return 1.0f - __fdividef(2.0f, __expf(2.0f * x) + 1.0f);
}

// ---------------------------------------------------------------------------
// GEMM: C[m][n] = sum_k X[m][k]*W[n][k] + bias[n];  M=65536, N=768, K=256.
// 64x64 tile, 256 threads, 4x4 fragments, f32x2 packed FMAs. (unchanged)
// ---------------------------------------------------------------------------
__global__ void __launch_bounds__(256)
gemm768_kernel(const float* __restrict__ X, int lda,
               const float* __restrict__ W,
               const float* __restrict__ bias)
{
    __shared__ __align__(16) float Xs[64 * 70];
    __shared__ __align__(16) float Ws[64 * 70];

    const int tid = threadIdx.x;
    const int tx = tid & 15;
    const int ty = tid >> 4;
    const int m0 = blockIdx.y * 64;
    const int n0 = blockIdx.x * 64;

    const int kq = tid & 15;
    const int rr = tid >> 4;

    uint64_t acc[4][4] = {};

    for (int kc = 0; kc < 256; kc += 64) {
#pragma unroll
        for (int jj = 0; jj < 4; jj++) {
            int row = rr + 16 * jj;
            float4 xv = *(const float4*)&X[(size_t)(m0 + row) * lda + kc + kq * 4];
            float4 wv = *(const float4*)&W[(size_t)(n0 + row) * 256 + kc + kq * 4];
            *(float2*)&Xs[row * 70 + kq * 4]     = make_float2(xv.x, xv.y);
            *(float2*)&Xs[row * 70 + kq * 4 + 2] = make_float2(xv.z, xv.w);
            *(float2*)&Ws[row * 70 + kq * 4]     = make_float2(wv.x, wv.y);
            *(float2*)&Ws[row * 70 + kq * 4 + 2] = make_float2(wv.z, wv.w);
        }
        __syncthreads();

#pragma unroll 8
        for (int kp = 0; kp < 32; kp++) {
            uint64_t xf[4], wf[4];
#pragma unroll
            for (int jj = 0; jj < 4; jj++)
                xf[jj] = *(const uint64_t*)&Xs[(ty + 16 * jj) * 70 + 2 * kp];
#pragma unroll
            for (int ii = 0; ii < 4; ii++)
                wf[ii] = *(const uint64_t*)&Ws[(tx + 16 * ii) * 70 + 2 * kp];
#pragma unroll
            for (int jj = 0; jj < 4; jj++)
#pragma unroll
                for (int ii = 0; ii < 4; ii++)
                    FMA2(acc[jj][ii], xf[jj], wf[ii], acc[jj][ii]);
        }
        __syncthreads();
    }

#pragma unroll
    for (int jj = 0; jj < 4; jj++) {
        int m = m0 + ty + 16 * jj;
#pragma unroll
        for (int ii = 0; ii < 4; ii++) {
            int n = n0 + tx + 16 * ii;
            float lo, hi;
            UNPK(lo, hi, acc[jj][ii]);
            g_xg[(size_t)m * Gn + n] = lo + hi + bias[n];
        }
    }
}

// ---------------------------------------------------------------------------
// Recurrence. Cluster of 4 CTAs = 2 batch rows; 32 clusters = 128 CTAs.
// Sync = per-step barrier.cluster (measured fastest vs mbarrier variants).
// Round-7 skeleton plus:
//  * gate duty on warps 8-11 (hi-wid arbiter priority -> they finish dot first)
//  * barrier split: arrive -> STG outputs + prefetch next xg -> wait
//  * 2-stage software-pipelined dot; pacc layout [kb][b][l] (all stride-1)
// ---------------------------------------------------------------------------
__global__ void __cluster_dims__(4, 1, 1) __launch_bounds__(384, 1)
gru_rec_kernel(const float* __restrict__ Whh,   // [768][256]
               const float* __restrict__ bhh,   // [768]
               float* __restrict__ outA, int pitchA, int colOffA,
               float* __restrict__ outB)        // second copy (pitch Hn) or null
{
    __shared__ __align__(16) float hb[2 * 2 * 256];  // [buf][batch][k]
    __shared__ float pacc[2 * 2 * 192];              // [kb][b][l]
    __shared__ float bh[192];

    const int tid = threadIdx.x;
    uint32_t rank;
    asm("mov.u32 %0, %%cluster_ctarank;" : "=r"(rank));
    const int cid   = blockIdx.x >> 2;
    const int b0    = cid * 2;
    const int cbase = (int)rank * 64;

    const int l   = tid % 192;
    const int kb  = tid / 192;            // 0 or 1
    const int kst = kb * 128;
    const int g   = (l < 64) ? (cbase + l)
                  : (l < 128) ? (256 + cbase + (l - 64))
                              : (512 + cbase + (l - 128));

    // ---- weights -> registers (64 x b64 = 128 floats per thread) ----
    uint64_t w[64];
    {
        const uint64_t* wsrc = (const uint64_t*)(Whh + (size_t)g * 256 + kst);
#pragma unroll
        for (int i = 0; i < 64; i++) w[i] = wsrc[i];
    }

    if (tid < 192) bh[l] = bhh[g];
    for (int i = tid; i < 1024; i += 384) hb[i] = 0.0f;   // h0 = 0, both bufs
    __syncthreads();

    // remote hb for the 3 peers
    uint32_t hb_local = (uint32_t)__cvta_generic_to_shared(hb);
    int peers[3];
#pragma unroll
    for (int p = 0; p < 3; p++) peers[p] = p + (p >= (int)rank ? 1 : 0);
    uint32_t remote_hb[3];
#pragma unroll
    for (int p = 0; p < 3; p++) {
        asm("mapa.shared::cluster.u32 %0, %1, %2;"
            : "=r"(remote_hb[p]) : "r"(hb_local), "r"(peers[p]));
    }

    // everyone's hb zeroed before any remote pushes
    asm volatile("barrier.cluster.arrive.aligned;" ::: "memory");
    asm volatile("barrier.cluster.wait.aligned;"   ::: "memory");

    // gate roles: warps 8-11 (tid 256..383) — hi-wid arbiter priority
    const bool  is_gate = (tid >= 256);
    const int   gt   = tid - 256;
    const int   j    = gt & 63;
    const int   bsel = (gt >> 6) & 1;
    const int   gcol = cbase + j;
    const float* xp = g_xg + ((size_t)(b0 + bsel) * Sn) * Gn + gcol;
    float* oA = outA + ((size_t)(b0 + bsel) * Sn) * pitchA + colOffA + gcol;
    float* oB = outB ? outB + ((size_t)(b0 + bsel) * Sn) * Hn + gcol : nullptr;

    // prologue xg prefetch (t = 0)
    float xr = 0.f, xz = 0.f, xn = 0.f;
    if (is_gate) {
        xr = __ldg(xp);
        xz = __ldg(xp + 256);
        xn = __ldg(xp + 512);
    }

    float hprev = 0.0f;   // own h column lives in a register (gate threads)

    for (int t = 0; t < Sn; t++) {
        const int cur = t & 1;
        const int nxt = cur ^ 1;
        const bool not_last = (t < Sn - 1);

        // ---- 2-stage pipelined packed dot (128-k half, both batch rows) ----
        const ulonglong2* h0p = (const ulonglong2*)(hb + cur * 512 + kst);
        const ulonglong2* h1p = (const ulonglong2*)(hb + cur * 512 + 256 + kst);
        uint64_t a0 = 0, a1 = 0, c0 = 0, c1 = 0;
        ulonglong2 hA = h0p[0], hB = h1p[0];
#pragma unroll
        for (int i = 0; i < 31; i++) {
            ulonglong2 hA1 = h0p[i + 1];
            ulonglong2 hB1 = h1p[i + 1];
            FMA2(a0, w[2 * i],     hA.x, a0);
            FMA2(a1, w[2 * i + 1], hA.y, a1);
            FMA2(c0, w[2 * i],     hB.x, c0);
            FMA2(c1, w[2 * i + 1], hB.y, c1);
            hA = hA1; hB = hB1;
        }
        FMA2(a0, w[62], hA.x, a0);
        FMA2(a1, w[63], hA.y, a1);
        FMA2(c0, w[62], hB.x, c0);
        FMA2(c1, w[63], hB.y, c1);

        uint64_t s0, s1;
        ADD2(s0, a0, a1);
        ADD2(s1, c0, c1);
        float s0l, s0h, s1l, s1h;
        UNPK(s0l, s0h, s0);
        UNPK(s1l, s1h, s1);
        pacc[kb * 384 + l]       = s0l + s0h;   // [kb][b=0][l]
        pacc[kb * 384 + 192 + l] = s1l + s1h;   // [kb][b=1][l]
        __syncthreads();

        // ---- gates + state update (warps 8-11: 64 cols x 2 batch) ----
        float hnew = 0.f;
        if (is_gate) {
            const float* pa = pacc + bsel * 192;
            float hr = pa[j]       + pa[384 + j]       + bh[j];
            float hz = pa[64 + j]  + pa[384 + 64 + j]  + bh[64 + j];
            float hn = pa[128 + j] + pa[384 + 128 + j] + bh[128 + j];

            float r = sigmoid_f(xr + hr);
            float z = sigmoid_f(xz + hz);
            float n = tanh_f(xn + r * hn);

            hnew  = (1.0f - z) * n + z * hprev;
            hprev = hnew;

            if (not_last) {
                uint32_t off = (uint32_t)((nxt * 512 + bsel * 256 + gcol) * 4);
                hb[nxt * 512 + bsel * 256 + gcol] = hnew;
#pragma unroll
                for (int p = 0; p < 3; p++) {
                    asm volatile("st.shared::cluster.f32 [%0], %1;"
                                 :: "r"(remote_hb[p] + off), "f"(hnew));
                }
            }
        }

        // release own slice to the cluster; overlap output + prefetch with wait
        asm volatile("barrier.cluster.arrive.aligned;" ::: "memory");

        if (is_gate) {
            *oA = hnew;
            oA += pitchA;
            if (oB) { *oB = hnew; oB += Hn; }
            if (not_last) {          // prefetch next step's xg (DRAM latency
                xp += Gn;            //  hidden under the barrier wait + dot)
                xr = __ldg(xp);
                xz = __ldg(xp + 256);
                xn = __ldg(xp + 512);
            }
        }

        asm volatile("barrier.cluster.wait.aligned;" ::: "memory");
    }
    // After the final barrier no CTA issues remote ops -> safe to exit.
}

// ---------------------------------------------------------------------------
// Launch: GEMM0 -> REC0 -> GEMM1 -> REC1.
// Output layout (tuple flattened): [ h2 (B,S,H) | concat(h1,h2) (B,S,2H) ].
// ---------------------------------------------------------------------------
extern "C" void kernel_launch(void* const* d_in, const int* in_sizes, int n_in,
                              void* d_out, int out_size)
{
    const float* inputs = (const float*)d_in[0];
    const float* W_ih0  = (const float*)d_in[1];
    const float* W_hh0  = (const float*)d_in[2];
    const float* b_ih0  = (const float*)d_in[3];
    const float* b_hh0  = (const float*)d_in[4];
    const float* W_ih1  = (const float*)d_in[5];
    const float* W_hh1  = (const float*)d_in[6];
    const float* b_ih1  = (const float*)d_in[7];
    const float* b_hh1  = (const float*)d_in[8];

    float* out    = (float*)d_out;
    float* h2     = out;                              // [B,S,H]
    float* concat = out + (size_t)Bn * Sn * Hn;       // [B,S,2H]

    (void)in_sizes; (void)n_in; (void)out_size;

    dim3 ggrid(Gn / 64, (Bn * Sn) / 64);   // 12 x 1024

    // Layer 0
    gemm768_kernel<<<ggrid, 256>>>(inputs, In, W_ih0, b_ih0);
    gru_rec_kernel<<<128, 384>>>(W_hh0, b_hh0, concat, 2 * Hn, 0, nullptr);

    // Layer 1: input is h1 living in concat (row pitch 512, cols 0..255)
    gemm768_kernel<<<ggrid, 256>>>(concat, 2 * Hn, W_ih1, b_ih1);
    gru_rec_kernel<<<128, 384>>>(W_hh1, b_hh1, concat, 2 * Hn, Hn, h2);
}